// round 6
// baseline (speedup 1.0000x reference)
#include <cuda_runtime.h>
#include <math.h>

// Shapes (fixed):
//   x  : [B=8, C=128, D=4, H=128, W=128] -> 67,108,864 fp32 (256 MB)
//   w1, w2 : [C, C] row-major (w[o,c] = w[o*128 + c]); b1, b2 : [C]
// out = x * sigmoid(W2 @ relu(W1 @ max_{dhw}(x) + b1) + b2), gate per (b,c).

#define BC 1024              // B*C slices
#define SLICE4 16384         // 65536 floats / 4 per (b,c)

__device__ float d_gp[BC];             // per-(b,c) global max
__device__ float d_gate[BC];           // per-(b,c) sigmoid gate
__device__ unsigned int d_counter = 0; // last-block ticket (reset by last block)

// ---------------- Kernel 1: per-slice max reduce + fused MLP in last block ----
// One block per (b,c) slice. 256 threads x 64 float4, coalesced.
// Default cache policy (NOT streaming): leaves the tail of x hot in L2 for
// the scale kernel's reverse-order re-read.
__global__ __launch_bounds__(256) void reduce_mlp_kernel(const float4* __restrict__ x4,
                                                         const float* __restrict__ w1,
                                                         const float* __restrict__ b1,
                                                         const float* __restrict__ w2,
                                                         const float* __restrict__ b2) {
    const int bc = blockIdx.x;
    const float4* base = x4 + (size_t)bc * SLICE4;
    const int t = threadIdx.x;

    float m0 = -INFINITY, m1 = -INFINITY, m2 = -INFINITY, m3 = -INFINITY;
    #pragma unroll
    for (int i = 0; i < 16; i++) {
        float4 a = base[t + (4 * i + 0) * 256];
        float4 b = base[t + (4 * i + 1) * 256];
        float4 c = base[t + (4 * i + 2) * 256];
        float4 d = base[t + (4 * i + 3) * 256];
        m0 = fmaxf(m0, fmaxf(fmaxf(a.x, a.y), fmaxf(a.z, a.w)));
        m1 = fmaxf(m1, fmaxf(fmaxf(b.x, b.y), fmaxf(b.z, b.w)));
        m2 = fmaxf(m2, fmaxf(fmaxf(c.x, c.y), fmaxf(c.z, c.w)));
        m3 = fmaxf(m3, fmaxf(fmaxf(d.x, d.y), fmaxf(d.z, d.w)));
    }
    float m = fmaxf(fmaxf(m0, m1), fmaxf(m2, m3));

    #pragma unroll
    for (int off = 16; off > 0; off >>= 1)
        m = fmaxf(m, __shfl_xor_sync(0xFFFFFFFFu, m, off));

    __shared__ float s_red[8];
    if ((t & 31) == 0) s_red[t >> 5] = m;
    __syncthreads();
    if (t == 0) {
        float r = s_red[0];
        #pragma unroll
        for (int w = 1; w < 8; w++) r = fmaxf(r, s_red[w]);
        d_gp[bc] = r;
    }

    // ---- last-block ticket: the final block computes the whole MLP ----
    __shared__ unsigned s_ticket;
    __threadfence();  // publish d_gp[bc] before incrementing the counter
    if (t == 0) s_ticket = atomicAdd(&d_counter, 1);
    __syncthreads();
    if (s_ticket != BC - 1) return;

    if (t == 0) d_counter = 0;  // reset for next graph replay (we are the only block left)
    __threadfence();            // acquire: make all blocks' d_gp writes visible (flushes L1D)

    __shared__ float s_gp[8 * 128];
    __shared__ float s_h[8 * 128];
    for (int i = t; i < BC; i += 256) s_gp[i] = d_gp[i];
    __syncthreads();

    // 256 threads: o = output channel, half selects batches 0-3 / 4-7.
    const int o = t & 127;
    const int half = t >> 7;
    const float* w1row = w1 + o * 128;   // L1-cached after first touch
    const float* w2row = w2 + o * 128;
    const float bias1 = b1[o];
    const float bias2 = b2[o];

    #pragma unroll
    for (int bi = 0; bi < 4; bi++) {
        const int b = half * 4 + bi;
        const float* g = s_gp + b * 128;
        float a0 = 0.f, a1 = 0.f, a2 = 0.f, a3 = 0.f;
        #pragma unroll 8
        for (int c = 0; c < 128; c += 4) {
            a0 = fmaf(g[c + 0], w1row[c + 0], a0);
            a1 = fmaf(g[c + 1], w1row[c + 1], a1);
            a2 = fmaf(g[c + 2], w1row[c + 2], a2);
            a3 = fmaf(g[c + 3], w1row[c + 3], a3);
        }
        s_h[b * 128 + o] = fmaxf((a0 + a1) + (a2 + a3) + bias1, 0.0f);
    }
    __syncthreads();

    #pragma unroll
    for (int bi = 0; bi < 4; bi++) {
        const int b = half * 4 + bi;
        const float* h = s_h + b * 128;
        float a0 = 0.f, a1 = 0.f, a2 = 0.f, a3 = 0.f;
        #pragma unroll 8
        for (int c = 0; c < 128; c += 4) {
            a0 = fmaf(h[c + 0], w2row[c + 0], a0);
            a1 = fmaf(h[c + 1], w2row[c + 1], a1);
            a2 = fmaf(h[c + 2], w2row[c + 2], a2);
            a3 = fmaf(h[c + 3], w2row[c + 3], a3);
        }
        float z = (a0 + a1) + (a2 + a3) + bias2;
        d_gate[b * 128 + o] = 1.0f / (1.0f + __expf(-z));
    }
}

// ---------------- Kernel 2: broadcast scale, REVERSE slice order ----------------
// Processes slices 1023..0 so its first waves re-read the tail of x that the
// reduce kernel left hot in L2. Loads default policy (want L2 hits); stores
// evict-first (out never re-read, don't displace x lines).
__global__ __launch_bounds__(256) void scale_kernel(const float4* __restrict__ x4,
                                                    float4* __restrict__ o4) {
    const int bc = (BC - 1) - blockIdx.x;
    const float g = d_gate[bc];
    const float4* src = x4 + (size_t)bc * SLICE4;
    float4* dst = o4 + (size_t)bc * SLICE4;
    const int t = threadIdx.x;

    #pragma unroll
    for (int i = 0; i < 64; i++) {
        float4 v = src[t + i * 256];
        v.x *= g; v.y *= g; v.z *= g; v.w *= g;
        __stcs(dst + t + i * 256, v);
    }
}

extern "C" void kernel_launch(void* const* d_in, const int* in_sizes, int n_in,
                              void* d_out, int out_size) {
    const float* x  = (const float*)d_in[0];
    const float* w1 = (const float*)d_in[1];
    const float* b1 = (const float*)d_in[2];
    const float* w2 = (const float*)d_in[3];
    const float* b2 = (const float*)d_in[4];
    float* out = (float*)d_out;

    reduce_mlp_kernel<<<BC, 256>>>((const float4*)x, w1, b1, w2, b2);
    scale_kernel<<<BC, 256>>>((const float4*)x, (float4*)out);
}

// round 8
// speedup vs baseline: 1.9773x; 1.9773x over previous
#include <cuda_runtime.h>
#include <math.h>

// Shapes (fixed):
//   x  : [B=8, C=128, D=4, H=128, W=128] -> 67,108,864 fp32 (256 MB)
//   w1, w2 : [C, C] row-major (w[o,c] = w[o*128 + c]); b1, b2 : [C]
// out = x * sigmoid(W2 @ relu(W1 @ max_{dhw}(x) + b1) + b2), gate per (b,c).

#define BC 1024              // B*C slices
#define SLICE4 16384         // 65536 floats / 4 per (b,c)
#define C 128
#define CP 129               // padded row for conflict-free smem

__device__ float d_gp[BC];    // per-(b,c) global max
__device__ float d_gate[BC];  // per-(b,c) sigmoid gate

// ---------------- Kernel 1: per-slice max reduce ----------------
// One block per (b,c) slice. 256 threads x 64 float4, coalesced.
// Default cache policy: leaves the tail of x hot in L2 for kernel 3.
__global__ __launch_bounds__(256) void max_reduce_kernel(const float4* __restrict__ x4) {
    const int bc = blockIdx.x;
    const float4* base = x4 + (size_t)bc * SLICE4;
    const int t = threadIdx.x;

    float m0 = -INFINITY, m1 = -INFINITY, m2 = -INFINITY, m3 = -INFINITY;
    #pragma unroll
    for (int i = 0; i < 16; i++) {
        float4 a = base[t + (4 * i + 0) * 256];
        float4 b = base[t + (4 * i + 1) * 256];
        float4 c = base[t + (4 * i + 2) * 256];
        float4 d = base[t + (4 * i + 3) * 256];
        m0 = fmaxf(m0, fmaxf(fmaxf(a.x, a.y), fmaxf(a.z, a.w)));
        m1 = fmaxf(m1, fmaxf(fmaxf(b.x, b.y), fmaxf(b.z, b.w)));
        m2 = fmaxf(m2, fmaxf(fmaxf(c.x, c.y), fmaxf(c.z, c.w)));
        m3 = fmaxf(m3, fmaxf(fmaxf(d.x, d.y), fmaxf(d.z, d.w)));
    }
    float m = fmaxf(fmaxf(m0, m1), fmaxf(m2, m3));

    #pragma unroll
    for (int off = 16; off > 0; off >>= 1)
        m = fmaxf(m, __shfl_xor_sync(0xFFFFFFFFu, m, off));

    __shared__ float s[8];
    if ((t & 31) == 0) s[t >> 5] = m;
    __syncthreads();
    if (t == 0) {
        float r = s[0];
        #pragma unroll
        for (int w = 1; w < 8; w++) r = fmaxf(r, s[w]);
        d_gp[bc] = r;
    }
}

// ---------------- Kernel 2: tiny MLP gate (proven R5 version) ----------------
// One block per batch (grid=8), 128 threads (thread = output channel o).
// Weights staged to smem transposed: s_w[c*129 + o] = w[o*128 + c].
__global__ __launch_bounds__(128) void mlp_gate_kernel(const float* __restrict__ w1,
                                                       const float* __restrict__ b1,
                                                       const float* __restrict__ w2,
                                                       const float* __restrict__ b2) {
    __shared__ float s_w1[C * CP];
    __shared__ float s_w2[C * CP];
    __shared__ float s_gp[C];
    __shared__ float s_h[C];

    const int b = blockIdx.x;
    const int o = threadIdx.x;

    // coalesced load + transpose into smem
    #pragma unroll
    for (int i = 0; i < C; i++) {
        int idx = i * 128 + o;          // linear over w -> coalesced
        int r = idx >> 7;               // source row (output channel)
        int cc = idx & 127;             // source col (input channel)
        s_w1[cc * CP + r] = w1[idx];
        s_w2[cc * CP + r] = w2[idx];
    }
    s_gp[o] = d_gp[b * C + o];
    __syncthreads();

    // layer 1: h[o] = relu(sum_c gp[c] * w1[o,c] + b1[o])
    {
        float a0 = 0.f, a1 = 0.f, a2 = 0.f, a3 = 0.f;
        #pragma unroll
        for (int c = 0; c < C; c += 4) {
            a0 = fmaf(s_gp[c + 0], s_w1[(c + 0) * CP + o], a0);
            a1 = fmaf(s_gp[c + 1], s_w1[(c + 1) * CP + o], a1);
            a2 = fmaf(s_gp[c + 2], s_w1[(c + 2) * CP + o], a2);
            a3 = fmaf(s_gp[c + 3], s_w1[(c + 3) * CP + o], a3);
        }
        s_h[o] = fmaxf((a0 + a1) + (a2 + a3) + b1[o], 0.0f);
    }
    __syncthreads();

    // layer 2: gate[o] = sigmoid(sum_c h[c] * w2[o,c] + b2[o])
    {
        float a0 = 0.f, a1 = 0.f, a2 = 0.f, a3 = 0.f;
        #pragma unroll
        for (int c = 0; c < C; c += 4) {
            a0 = fmaf(s_h[c + 0], s_w2[(c + 0) * CP + o], a0);
            a1 = fmaf(s_h[c + 1], s_w2[(c + 1) * CP + o], a1);
            a2 = fmaf(s_h[c + 2], s_w2[(c + 2) * CP + o], a2);
            a3 = fmaf(s_h[c + 3], s_w2[(c + 3) * CP + o], a3);
        }
        float z = (a0 + a1) + (a2 + a3) + b2[o];
        d_gate[b * C + o] = 1.0f / (1.0f + __expf(-z));
    }
}

// ---------------- Kernel 3: broadcast scale, REVERSE slice order ----------------
// Slices 1023..0: first waves re-read the tail of x left hot in L2 by kernel 1.
// Loads default policy (want L2 hits); stores evict-first (out never re-read).
__global__ __launch_bounds__(256) void scale_kernel(const float4* __restrict__ x4,
                                                    float4* __restrict__ o4) {
    const int bc = (BC - 1) - blockIdx.x;
    const float g = d_gate[bc];
    const float4* src = x4 + (size_t)bc * SLICE4;
    float4* dst = o4 + (size_t)bc * SLICE4;
    const int t = threadIdx.x;

    #pragma unroll
    for (int i = 0; i < 64; i++) {
        float4 v = src[t + i * 256];
        v.x *= g; v.y *= g; v.z *= g; v.w *= g;
        __stcs(dst + t + i * 256, v);
    }
}

extern "C" void kernel_launch(void* const* d_in, const int* in_sizes, int n_in,
                              void* d_out, int out_size) {
    const float* x  = (const float*)d_in[0];
    const float* w1 = (const float*)d_in[1];
    const float* b1 = (const float*)d_in[2];
    const float* w2 = (const float*)d_in[3];
    const float* b2 = (const float*)d_in[4];
    float* out = (float*)d_out;

    max_reduce_kernel<<<BC, 256>>>((const float4*)x);
    mlp_gate_kernel<<<8, 128>>>(w1, b1, w2, b2);
    scale_kernel<<<BC, 256>>>((const float4*)x, (float4*)out);
}